// round 14
// baseline (speedup 1.0000x reference)
#include <cuda_runtime.h>
#include <cuda_fp16.h>

#define NMAX 100000
#define EMAX 1600000
#define SCAN_BLK 256
#define MAX_BLOCKS 512   // ceil(NMAX/SCAN_BLK) = 391 <= 512
#define WSTR 136         // padded stride for transposed W (halves)

// Scratch (allocation-free rule: __device__ globals)
__device__ int   g_is64;
__device__ int   g_deg[NMAX];
__device__ float g_dinv[NMAX];
__device__ int   g_off[NMAX];
__device__ int   g_cur[NMAX];
__device__ unsigned long long g_part[MAX_BLOCKS];  // lookback: (flag<<32)|sum
__device__ unsigned long long g_csr2[EMAX];        // packed (src | dinv[src]<<32)
__device__ __align__(16) __half g_t16[NMAX * 64];  // t in fp16 (gather matrix)
__device__ __align__(16) __half g_h16[NMAX * 64];  // relu(agg1+b1) in fp16
__device__ __align__(16) __half g_W1t[64 * WSTR];  // W1^T fp16, padded
__device__ __align__(16) __half g_W2t[64 * WSTR];  // W2^T fp16, padded

// ---------------------------------------------------------------------------
__global__ void k_init(const unsigned int* __restrict__ w, int n) {
    int i = blockIdx.x * 1024 + threadIdx.x;
    if (i < n) g_deg[i] = 1;  // self-loop
    if (i < MAX_BLOCKS) g_part[i] = 0ull;   // reset lookback state each replay
    if (blockIdx.x == 0) {
        int nz = (w[2 * threadIdx.x + 1] != 0u) ? 1 : 0;
        int tot = __syncthreads_count(nz);
        if (threadIdx.x == 0) g_is64 = (tot == 0) ? 1 : 0;
    }
}

__global__ void k_prep_w(const float* __restrict__ W1,
                         const float* __restrict__ W2) {
    int i = blockIdx.x * 256 + threadIdx.x;
    if (i < 64 * 128) {
        int nn = i >> 7, k = i & 127;
        g_W1t[nn * WSTR + k] = __float2half(W1[k * 64 + nn]);
    } else if (i < 64 * 128 + 64 * 64) {
        int j = i - 64 * 128;
        int nn = j >> 6, k = j & 63;
        g_W2t[nn * WSTR + k] = __float2half(W2[k * 64 + nn]);
    }
}

__device__ __forceinline__ int load_idx(const void* ei, long long i) {
    if (g_is64) return (int)((const long long*)ei)[i];
    return ((const int*)ei)[i];
}

// 8 edges per thread (2x int4 on the int32 fast path) for MLP.
__global__ void k_count(const void* __restrict__ ei, int e, int n) {
    int i8 = (blockIdx.x * blockDim.x + threadIdx.x) * 8;
    if (i8 >= e) return;
    if (!g_is64 && i8 + 8 <= e) {
        int4 d0 = *(const int4*)((const int*)ei + e + i8);
        int4 d1 = *(const int4*)((const int*)ei + e + i8 + 4);
        int d[8] = {d0.x, d0.y, d0.z, d0.w, d1.x, d1.y, d1.z, d1.w};
#pragma unroll
        for (int j = 0; j < 8; j++)
            if ((unsigned)d[j] < (unsigned)n) atomicAdd(&g_deg[d[j]], 1);
    } else {
        for (int i = i8; i < i8 + 8 && i < e; i++) {
            int d = load_idx(ei, (long long)e + i);
            if ((unsigned)d < (unsigned)n) atomicAdd(&g_deg[d], 1);
        }
    }
}

// --- single-pass decoupled-lookback exclusive scan of (deg-1) --------------
// Packed state word: flag in [32:34) (1=aggregate ready, 2=prefix ready),
// value in [0:32). Published via atomicExch (single-word atomicity).
__global__ void k_scanlb(int n) {
    __shared__ int sh[SCAN_BLK];
    __shared__ int s_prefix;
    int t = threadIdx.x;
    int b = blockIdx.x;
    int i = b * SCAN_BLK + t;
    int d = (i < n) ? g_deg[i] : 1;
    int v = d - 1;
    sh[t] = v;
    __syncthreads();
    for (int ofs = 1; ofs < SCAN_BLK; ofs <<= 1) {
        int add = (t >= ofs) ? sh[t - ofs] : 0;
        __syncthreads();
        sh[t] += add;
        __syncthreads();
    }
    int total = sh[SCAN_BLK - 1];

    if (b == 0) {
        if (t == 0) {
            s_prefix = 0;
            atomicExch(&g_part[0], (2ull << 32) | (unsigned)total);
        }
    } else {
        if (t == 0)
            atomicExch(&g_part[b], (1ull << 32) | (unsigned)total);
        if (t < 32) {
            int prefix = 0;
            int look = b - 1;
            while (true) {
                int idx = look - t;
                unsigned long long p =
                    (idx >= 0) ? *(volatile unsigned long long*)&g_part[idx]
                               : (2ull << 32);
                unsigned flag = (unsigned)(p >> 32);
                int val = (int)(unsigned)p;
                unsigned pmask = __ballot_sync(0xFFFFFFFFu, flag == 2u);
                unsigned zmask = __ballot_sync(0xFFFFFFFFu, flag == 0u);
                if (pmask != 0) {
                    int firstP = __ffs(pmask) - 1;   // closest prefix
                    unsigned before = (firstP == 31) ? 0x7FFFFFFFu
                                                     : ((1u << firstP) - 1u);
                    if ((zmask & before) == 0) {
                        int contrib = (t <= firstP) ? val : 0;
#pragma unroll
                        for (int o = 16; o > 0; o >>= 1)
                            contrib += __shfl_down_sync(0xFFFFFFFFu, contrib, o);
                        prefix += __shfl_sync(0xFFFFFFFFu, contrib, 0);
                        break;
                    }
                } else if (zmask == 0) {
                    int contrib = val;
#pragma unroll
                    for (int o = 16; o > 0; o >>= 1)
                        contrib += __shfl_down_sync(0xFFFFFFFFu, contrib, o);
                    prefix += __shfl_sync(0xFFFFFFFFu, contrib, 0);
                    look -= 32;
                }
            }
            if (t == 0) {
                s_prefix = prefix;
                atomicExch(&g_part[b], (2ull << 32) | (unsigned)(prefix + total));
            }
        }
    }
    __syncthreads();
    if (i < n) {
        int off = s_prefix + sh[t] - v;  // exclusive
        g_off[i] = off;
        g_cur[i] = off;
        g_dinv[i] = rsqrtf((float)d);
    }
}

__global__ void k_fill(const void* __restrict__ ei, int e, int n) {
    int i4 = (blockIdx.x * blockDim.x + threadIdx.x) * 4;
    if (i4 >= e) return;
    if (!g_is64 && i4 + 4 <= e) {
        int4 s = *(const int4*)((const int*)ei + i4);
        int4 d = *(const int4*)((const int*)ei + e + i4);
        int ss[4] = {s.x, s.y, s.z, s.w};
        int dd[4] = {d.x, d.y, d.z, d.w};
#pragma unroll
        for (int j = 0; j < 4; j++) {
            if ((unsigned)ss[j] >= (unsigned)n || (unsigned)dd[j] >= (unsigned)n)
                continue;
            int pos = atomicAdd(&g_cur[dd[j]], 1);
            if ((unsigned)pos < (unsigned)EMAX)
                g_csr2[pos] = (unsigned long long)(unsigned)ss[j] |
                              ((unsigned long long)__float_as_uint(g_dinv[ss[j]]) << 32);
        }
    } else {
        for (int i = i4; i < i4 + 4 && i < e; i++) {
            int s = load_idx(ei, i);
            int d = load_idx(ei, (long long)e + i);
            if ((unsigned)s >= (unsigned)n || (unsigned)d >= (unsigned)n) continue;
            int pos = atomicAdd(&g_cur[d], 1);
            if ((unsigned)pos < (unsigned)EMAX)
                g_csr2[pos] = (unsigned long long)(unsigned)s |
                              ((unsigned long long)__float_as_uint(g_dinv[s]) << 32);
        }
    }
}

// --- HMMA / LDSM helpers ---------------------------------------------------
__device__ __forceinline__ void mma16816(float c[4], const unsigned a[4],
                                         const unsigned b[2]) {
    asm volatile(
        "mma.sync.aligned.m16n8k16.row.col.f32.f16.f16.f32 "
        "{%0,%1,%2,%3}, {%4,%5,%6,%7}, {%8,%9}, {%0,%1,%2,%3};"
        : "+f"(c[0]), "+f"(c[1]), "+f"(c[2]), "+f"(c[3])
        : "r"(a[0]), "r"(a[1]), "r"(a[2]), "r"(a[3]), "r"(b[0]), "r"(b[1]));
}

__device__ __forceinline__ void ldsm_x4(unsigned r[4], unsigned addr) {
    asm volatile(
        "ldmatrix.sync.aligned.m8n8.x4.shared.b16 {%0,%1,%2,%3}, [%4];"
        : "=r"(r[0]), "=r"(r[1]), "=r"(r[2]), "=r"(r[3]) : "r"(addr));
}

__device__ __forceinline__ unsigned smem_u32(const void* p) {
    return (unsigned)__cvta_generic_to_shared(p);
}

__device__ __forceinline__ uint4 cvt8(float4 v0, float4 v1) {
    uint4 u;
    __half2 h0 = __floats2half2_rn(v0.x, v0.y);
    __half2 h1 = __floats2half2_rn(v0.z, v0.w);
    __half2 h2 = __floats2half2_rn(v1.x, v1.y);
    __half2 h3 = __floats2half2_rn(v1.z, v1.w);
    u.x = *(unsigned*)&h0; u.y = *(unsigned*)&h1;
    u.z = *(unsigned*)&h2; u.w = *(unsigned*)&h3;
    return u;
}

// ---------------------------------------------------------------------------
// GEMM1 (HMMA+LDSM, pipelined): g_t16 = half(x @ W1).
__global__ void __launch_bounds__(256) k_gemm1(const float* __restrict__ x,
                                               int n) {
    __shared__ __half As[128 * 72];
    __shared__ __half Wt[64 * WSTR];
    int tid = threadIdx.x, lane = tid & 31, wid = tid >> 5;
    int row0 = blockIdx.x * 128;
    int wr = wid & 3, wc = wid >> 2;
    int gq = lane >> 2, tq = lane & 3;
    int sub = lane >> 3, lr8 = lane & 7;

    {
        const uint4* wsrc = (const uint4*)g_W1t;
        uint4* wdst = (uint4*)Wt;
        for (int i = tid; i < 64 * WSTR / 8; i += 256) wdst[i] = wsrc[i];
    }

    unsigned a_base[2];
    {
        int arow = wr * 32 + ((sub & 1) ? 8 : 0) + lr8;
        int acol = (sub & 2) ? 8 : 0;
        a_base[0] = smem_u32(As + arow * 72 + acol);
        a_base[1] = a_base[0] + 16 * 72 * 2;
    }
    unsigned b_base[2];
    {
        int brow = wc * 32 + ((sub & 2) ? 8 : 0) + lr8;
        int bcol = (sub & 1) ? 8 : 0;
        b_base[0] = smem_u32(Wt + brow * WSTR + bcol);
        b_base[1] = b_base[0] + 16 * WSTR * 2;
    }

    float c[2][4][4];
#pragma unroll
    for (int ms = 0; ms < 2; ms++)
#pragma unroll
        for (int ns = 0; ns < 4; ns++)
#pragma unroll
            for (int q = 0; q < 4; q++) c[ms][ns][q] = 0.f;

    int lr = tid >> 1, lh = tid & 1;
    const float4* src0 =
        (const float4*)(x + (long long)(row0 + lr) * 128 + lh * 32);
    const float4* src1 = src0 + 16;
    bool ok = (row0 + lr) < n;
    uint4* dst = (uint4*)(As + lr * 72 + lh * 32);

    {
        float4 v[8];
#pragma unroll
        for (int q = 0; q < 8; q++)
            v[q] = ok ? src0[q] : make_float4(0.f, 0.f, 0.f, 0.f);
#pragma unroll
        for (int q = 0; q < 4; q++) dst[q] = cvt8(v[2 * q], v[2 * q + 1]);
    }
    float4 p[8];
#pragma unroll
    for (int q = 0; q < 8; q++)
        p[q] = ok ? src1[q] : make_float4(0.f, 0.f, 0.f, 0.f);

    __syncthreads();
#pragma unroll
    for (int ks = 0; ks < 4; ks++) {
        unsigned a[2][4], bb[2][4];
#pragma unroll
        for (int ms = 0; ms < 2; ms++) ldsm_x4(a[ms], a_base[ms] + ks * 32);
#pragma unroll
        for (int np = 0; np < 2; np++) ldsm_x4(bb[np], b_base[np] + ks * 32);
#pragma unroll
        for (int ms = 0; ms < 2; ms++)
#pragma unroll
            for (int np = 0; np < 2; np++) {
                mma16816(c[ms][np * 2],     a[ms], &bb[np][0]);
                mma16816(c[ms][np * 2 + 1], a[ms], &bb[np][2]);
            }
    }
    __syncthreads();
#pragma unroll
    for (int q = 0; q < 4; q++) dst[q] = cvt8(p[2 * q], p[2 * q + 1]);
    __syncthreads();
#pragma unroll
    for (int ks = 0; ks < 4; ks++) {
        unsigned a[2][4], bb[2][4];
#pragma unroll
        for (int ms = 0; ms < 2; ms++) ldsm_x4(a[ms], a_base[ms] + ks * 32);
#pragma unroll
        for (int np = 0; np < 2; np++)
            ldsm_x4(bb[np], b_base[np] + (64 + ks * 16) * 2);
#pragma unroll
        for (int ms = 0; ms < 2; ms++)
#pragma unroll
            for (int np = 0; np < 2; np++) {
                mma16816(c[ms][np * 2],     a[ms], &bb[np][0]);
                mma16816(c[ms][np * 2 + 1], a[ms], &bb[np][2]);
            }
    }

#pragma unroll
    for (int ms = 0; ms < 2; ms++) {
        int r = row0 + wr * 32 + ms * 16 + gq;
#pragma unroll
        for (int ns = 0; ns < 4; ns++) {
            int col = wc * 32 + ns * 8 + 2 * tq;
            if (r < n)
                *(__half2*)(g_t16 + (long long)r * 64 + col) =
                    __floats2half2_rn(c[ms][ns][0], c[ms][ns][1]);
            if (r + 8 < n)
                *(__half2*)(g_t16 + (long long)(r + 8) * 64 + col) =
                    __floats2half2_rn(c[ms][ns][2], c[ms][ns][3]);
        }
    }
}

// GEMM2 (HMMA+LDSM): g_t16 = half(g_h16 @ W2). g_h16 already relu+biased.
__global__ void __launch_bounds__(256) k_gemm2(int n) {
    __shared__ __half As[128 * 72];
    __shared__ __half Wt[64 * WSTR];
    int tid = threadIdx.x, lane = tid & 31, wid = tid >> 5;
    int row0 = blockIdx.x * 128;
    int wr = wid & 3, wc = wid >> 2;
    int gq = lane >> 2, tq = lane & 3;
    int sub = lane >> 3, lr8 = lane & 7;

    {
        const uint4* wsrc = (const uint4*)g_W2t;
        uint4* wdst = (uint4*)Wt;
        for (int i = tid; i < 64 * WSTR / 8; i += 256) wdst[i] = wsrc[i];
    }

    {
        int lr = tid >> 1, lh = tid & 1;
        const uint4* src =
            (const uint4*)(g_h16 + (long long)(row0 + lr) * 64 + lh * 32);
        bool ok = (row0 + lr) < n;
        uint4* dst = (uint4*)(As + lr * 72 + lh * 32);
#pragma unroll
        for (int q = 0; q < 4; q++)
            dst[q] = ok ? src[q] : make_uint4(0, 0, 0, 0);
    }

    unsigned a_base[2];
    {
        int arow = wr * 32 + ((sub & 1) ? 8 : 0) + lr8;
        int acol = (sub & 2) ? 8 : 0;
        a_base[0] = smem_u32(As + arow * 72 + acol);
        a_base[1] = a_base[0] + 16 * 72 * 2;
    }
    unsigned b_base[2];
    {
        int brow = wc * 32 + ((sub & 2) ? 8 : 0) + lr8;
        int bcol = (sub & 1) ? 8 : 0;
        b_base[0] = smem_u32(Wt + brow * WSTR + bcol);
        b_base[1] = b_base[0] + 16 * WSTR * 2;
    }
    __syncthreads();

    float c[2][4][4];
#pragma unroll
    for (int ms = 0; ms < 2; ms++)
#pragma unroll
        for (int ns = 0; ns < 4; ns++)
#pragma unroll
            for (int q = 0; q < 4; q++) c[ms][ns][q] = 0.f;

#pragma unroll
    for (int ks = 0; ks < 4; ks++) {
        unsigned a[2][4], bb[2][4];
#pragma unroll
        for (int ms = 0; ms < 2; ms++) ldsm_x4(a[ms], a_base[ms] + ks * 32);
#pragma unroll
        for (int np = 0; np < 2; np++) ldsm_x4(bb[np], b_base[np] + ks * 32);
#pragma unroll
        for (int ms = 0; ms < 2; ms++)
#pragma unroll
            for (int np = 0; np < 2; np++) {
                mma16816(c[ms][np * 2],     a[ms], &bb[np][0]);
                mma16816(c[ms][np * 2 + 1], a[ms], &bb[np][2]);
            }
    }

#pragma unroll
    for (int ms = 0; ms < 2; ms++) {
        int r = row0 + wr * 32 + ms * 16 + gq;
#pragma unroll
        for (int ns = 0; ns < 4; ns++) {
            int col = wc * 32 + ns * 8 + 2 * tq;
            if (r < n)
                *(__half2*)(g_t16 + (long long)r * 64 + col) =
                    __floats2half2_rn(c[ms][ns][0], c[ms][ns][1]);
            if (r + 8 < n)
                *(__half2*)(g_t16 + (long long)(r + 8) * 64 + col) =
                    __floats2half2_rn(c[ms][ns][2], c[ms][ns][3]);
        }
    }
}

// ---------------------------------------------------------------------------
// Pull aggregation: 8 threads per dst node, masked uniform batches of 8.
__device__ __forceinline__ void acc8(float acc[8], uint4 v, float w) {
    const __half2* h = (const __half2*)&v;
#pragma unroll
    for (int q = 0; q < 4; q++) {
        float2 f = __half22float2(h[q]);
        acc[2 * q]     += f.x * w;
        acc[2 * q + 1] += f.y * w;
    }
}

// FINAL=false: h = relu(agg + bias) -> g_h16 (fp16)
// FINAL=true : out = agg + bias     -> out  (fp32)
template <bool FINAL>
__global__ void k_agg(int n, const float* __restrict__ bias,
                      float* __restrict__ out) {
    int gid = blockIdx.x * 32 + (threadIdx.x >> 3);
    int c = threadIdx.x & 7;
    if (gid >= n) return;
    int lane = threadIdx.x & 31;
    int gb = lane & 24;
    unsigned gmask = 0xFFu << gb;

    const uint4* t4 = (const uint4*)g_t16;
    float dd = g_dinv[gid];
    float acc[8];
#pragma unroll
    for (int q = 0; q < 8; q++) acc[q] = 0.f;
    acc8(acc, t4[gid * 8 + c], dd);          // self-loop (one dinv factor)

    int k = g_off[gid];
    int m = g_deg[gid] - 1;
    for (int base = 0; base < m; base += 8) {
        int j = base + c;
        unsigned long long pc = (j < m) ? g_csr2[k + j] : 0ull;
        uint4 v[8]; float w[8];
#pragma unroll
        for (int jj = 0; jj < 8; jj++) {
            unsigned long long pj = __shfl_sync(gmask, pc, gb + jj);
            w[jj] = __uint_as_float((unsigned)(pj >> 32));
            v[jj] = t4[(int)(unsigned)pj * 8 + c];
        }
#pragma unroll
        for (int jj = 0; jj < 8; jj++) acc8(acc, v[jj], w[jj]);
    }

    float4 b0 = ((const float4*)bias)[c * 2];
    float4 b1v = ((const float4*)bias)[c * 2 + 1];
    float4 o0 = make_float4(acc[0] * dd + b0.x, acc[1] * dd + b0.y,
                            acc[2] * dd + b0.z, acc[3] * dd + b0.w);
    float4 o1 = make_float4(acc[4] * dd + b1v.x, acc[5] * dd + b1v.y,
                            acc[6] * dd + b1v.z, acc[7] * dd + b1v.w);
    if (FINAL) {
        float4* dst = (float4*)(out + gid * 64 + c * 8);
        dst[0] = o0; dst[1] = o1;
    } else {
        o0.x = fmaxf(o0.x, 0.f); o0.y = fmaxf(o0.y, 0.f);
        o0.z = fmaxf(o0.z, 0.f); o0.w = fmaxf(o0.w, 0.f);
        o1.x = fmaxf(o1.x, 0.f); o1.y = fmaxf(o1.y, 0.f);
        o1.z = fmaxf(o1.z, 0.f); o1.w = fmaxf(o1.w, 0.f);
        ((uint4*)g_h16)[gid * 8 + c] = cvt8(o0, o1);
    }
}

// ---------------------------------------------------------------------------
extern "C" void kernel_launch(void* const* d_in, const int* in_sizes, int n_in,
                              void* d_out, int out_size) {
    const float* x  = (const float*)d_in[0];
    const void*  ei = d_in[1];
    const float* W1 = (const float*)d_in[2];
    const float* b1 = (const float*)d_in[3];
    const float* W2 = (const float*)d_in[4];
    const float* b2 = (const float*)d_in[5];
    float* out = (float*)d_out;

    int n = in_sizes[0] / 128;
    int e = in_sizes[1] / 2;
    int nb = (n + SCAN_BLK - 1) / SCAN_BLK;
    int e4 = (e + 3) / 4;
    int e8 = (e + 7) / 8;

    cudaStreamCaptureStatus cs = cudaStreamCaptureStatusNone;
    cudaStreamIsCapturing((cudaStream_t)0, &cs);
    bool fork = (cs == cudaStreamCaptureStatusActive);

    cudaStream_t s1 = 0;
    cudaEvent_t eF = 0, eJ = 0;
    if (fork) {
        cudaStreamCreateWithFlags(&s1, cudaStreamNonBlocking);
        cudaEventCreateWithFlags(&eF, cudaEventDisableTiming);
        cudaEventCreateWithFlags(&eJ, cudaEventDisableTiming);
        cudaEventRecord(eF, 0);
        cudaStreamWaitEvent(s1, eF, 0);
    }
    // Branch A (independent of edges): W transpose + GEMM1
    k_prep_w<<<48, 256, 0, s1>>>(W1, W2);
    k_gemm1<<<(n + 127) / 128, 256, 0, s1>>>(x, n);
    if (fork) cudaEventRecord(eJ, s1);

    // Branch B (edge prep)
    k_init<<<(n + 1023) / 1024, 1024>>>((const unsigned int*)ei, n);
    k_count<<<(e8 + 255) / 256, 256>>>(ei, e, n);
    k_scanlb<<<nb, SCAN_BLK>>>(n);
    k_fill<<<(e4 + 255) / 256, 256>>>(ei, e, n);

    if (fork) cudaStreamWaitEvent((cudaStream_t)0, eJ, 0);

    // Layer 1 aggregation (fused +b1, relu), then layer 2
    k_agg<false><<<(n + 31) / 32, 256>>>(n, b1, nullptr);
    k_gemm2<<<(n + 127) / 128, 256>>>(n);
    k_agg<true><<<(n + 31) / 32, 256>>>(n, b2, out);
}

// round 16
// speedup vs baseline: 1.0147x; 1.0147x over previous
#include <cuda_runtime.h>
#include <cuda_fp16.h>

#define NMAX 100000
#define EMAX 1600000
#define SCAN_BLK 256
#define MAX_BLOCKS 512   // ceil(NMAX/SCAN_BLK) = 391 <= 512
#define WSTR 136         // padded stride for transposed W (halves)

// Scratch (allocation-free rule: __device__ globals)
__device__ int   g_is64;
__device__ int   g_deg[NMAX];
__device__ float g_dinv[NMAX];
__device__ int   g_off[NMAX];
__device__ int   g_cur[NMAX];
__device__ unsigned long long g_part[MAX_BLOCKS];  // lookback: (flag<<32)|sum
__device__ unsigned long long g_csr2[EMAX];        // packed (src | dinv[src]<<32)
__device__ __align__(16) __half g_t16[NMAX * 64];  // t1 (layer-1 gather matrix)
__device__ __align__(16) __half g_t2[NMAX * 64];   // t2 (layer-2 gather matrix)
__device__ __align__(16) __half g_W1t[64 * WSTR];  // W1^T fp16, padded
__device__ __align__(16) __half g_W2t[64 * WSTR];  // W2^T fp16, padded

// ---------------------------------------------------------------------------
__global__ void k_init(const unsigned int* __restrict__ w, int n) {
    int i = blockIdx.x * 1024 + threadIdx.x;
    if (i < n) g_deg[i] = 1;  // self-loop
    if (i < MAX_BLOCKS) g_part[i] = 0ull;   // reset lookback state each replay
    if (blockIdx.x == 0) {
        int nz = (w[2 * threadIdx.x + 1] != 0u) ? 1 : 0;
        int tot = __syncthreads_count(nz);
        if (threadIdx.x == 0) g_is64 = (tot == 0) ? 1 : 0;
    }
}

__global__ void k_prep_w(const float* __restrict__ W1,
                         const float* __restrict__ W2) {
    int i = blockIdx.x * 256 + threadIdx.x;
    if (i < 64 * 128) {
        int nn = i >> 7, k = i & 127;
        g_W1t[nn * WSTR + k] = __float2half(W1[k * 64 + nn]);
    } else if (i < 64 * 128 + 64 * 64) {
        int j = i - 64 * 128;
        int nn = j >> 6, k = j & 63;
        g_W2t[nn * WSTR + k] = __float2half(W2[k * 64 + nn]);
    }
}

__device__ __forceinline__ int load_idx(const void* ei, long long i) {
    if (g_is64) return (int)((const long long*)ei)[i];
    return ((const int*)ei)[i];
}

// 4 edges per thread (int4 on the int32 fast path) — best measured config.
__global__ void k_count(const void* __restrict__ ei, int e, int n) {
    int i4 = (blockIdx.x * blockDim.x + threadIdx.x) * 4;
    if (i4 >= e) return;
    if (!g_is64 && i4 + 4 <= e) {
        int4 d = *(const int4*)((const int*)ei + e + i4);
        if ((unsigned)d.x < (unsigned)n) atomicAdd(&g_deg[d.x], 1);
        if ((unsigned)d.y < (unsigned)n) atomicAdd(&g_deg[d.y], 1);
        if ((unsigned)d.z < (unsigned)n) atomicAdd(&g_deg[d.z], 1);
        if ((unsigned)d.w < (unsigned)n) atomicAdd(&g_deg[d.w], 1);
    } else {
        for (int i = i4; i < i4 + 4 && i < e; i++) {
            int d = load_idx(ei, (long long)e + i);
            if ((unsigned)d < (unsigned)n) atomicAdd(&g_deg[d], 1);
        }
    }
}

// --- single-pass decoupled-lookback exclusive scan of (deg-1) --------------
__global__ void k_scanlb(int n) {
    __shared__ int sh[SCAN_BLK];
    __shared__ int s_prefix;
    int t = threadIdx.x;
    int b = blockIdx.x;
    int i = b * SCAN_BLK + t;
    int d = (i < n) ? g_deg[i] : 1;
    int v = d - 1;
    sh[t] = v;
    __syncthreads();
    for (int ofs = 1; ofs < SCAN_BLK; ofs <<= 1) {
        int add = (t >= ofs) ? sh[t - ofs] : 0;
        __syncthreads();
        sh[t] += add;
        __syncthreads();
    }
    int total = sh[SCAN_BLK - 1];

    if (b == 0) {
        if (t == 0) {
            s_prefix = 0;
            atomicExch(&g_part[0], (2ull << 32) | (unsigned)total);
        }
    } else {
        if (t == 0)
            atomicExch(&g_part[b], (1ull << 32) | (unsigned)total);
        if (t < 32) {
            int prefix = 0;
            int look = b - 1;
            while (true) {
                int idx = look - t;
                unsigned long long p =
                    (idx >= 0) ? *(volatile unsigned long long*)&g_part[idx]
                               : (2ull << 32);
                unsigned flag = (unsigned)(p >> 32);
                int val = (int)(unsigned)p;
                unsigned pmask = __ballot_sync(0xFFFFFFFFu, flag == 2u);
                unsigned zmask = __ballot_sync(0xFFFFFFFFu, flag == 0u);
                if (pmask != 0) {
                    int firstP = __ffs(pmask) - 1;
                    unsigned before = (firstP == 31) ? 0x7FFFFFFFu
                                                     : ((1u << firstP) - 1u);
                    if ((zmask & before) == 0) {
                        int contrib = (t <= firstP) ? val : 0;
#pragma unroll
                        for (int o = 16; o > 0; o >>= 1)
                            contrib += __shfl_down_sync(0xFFFFFFFFu, contrib, o);
                        prefix += __shfl_sync(0xFFFFFFFFu, contrib, 0);
                        break;
                    }
                } else if (zmask == 0) {
                    int contrib = val;
#pragma unroll
                    for (int o = 16; o > 0; o >>= 1)
                        contrib += __shfl_down_sync(0xFFFFFFFFu, contrib, o);
                    prefix += __shfl_sync(0xFFFFFFFFu, contrib, 0);
                    look -= 32;
                }
            }
            if (t == 0) {
                s_prefix = prefix;
                atomicExch(&g_part[b], (2ull << 32) | (unsigned)(prefix + total));
            }
        }
    }
    __syncthreads();
    if (i < n) {
        int off = s_prefix + sh[t] - v;  // exclusive
        g_off[i] = off;
        g_cur[i] = off;
        g_dinv[i] = rsqrtf((float)d);
    }
}

__global__ void k_fill(const void* __restrict__ ei, int e, int n) {
    int i4 = (blockIdx.x * blockDim.x + threadIdx.x) * 4;
    if (i4 >= e) return;
    if (!g_is64 && i4 + 4 <= e) {
        int4 s = *(const int4*)((const int*)ei + i4);
        int4 d = *(const int4*)((const int*)ei + e + i4);
        int ss[4] = {s.x, s.y, s.z, s.w};
        int dd[4] = {d.x, d.y, d.z, d.w};
#pragma unroll
        for (int j = 0; j < 4; j++) {
            if ((unsigned)ss[j] >= (unsigned)n || (unsigned)dd[j] >= (unsigned)n)
                continue;
            int pos = atomicAdd(&g_cur[dd[j]], 1);
            if ((unsigned)pos < (unsigned)EMAX)
                g_csr2[pos] = (unsigned long long)(unsigned)ss[j] |
                              ((unsigned long long)__float_as_uint(g_dinv[ss[j]]) << 32);
        }
    } else {
        for (int i = i4; i < i4 + 4 && i < e; i++) {
            int s = load_idx(ei, i);
            int d = load_idx(ei, (long long)e + i);
            if ((unsigned)s >= (unsigned)n || (unsigned)d >= (unsigned)n) continue;
            int pos = atomicAdd(&g_cur[d], 1);
            if ((unsigned)pos < (unsigned)EMAX)
                g_csr2[pos] = (unsigned long long)(unsigned)s |
                              ((unsigned long long)__float_as_uint(g_dinv[s]) << 32);
        }
    }
}

// --- HMMA / LDSM helpers ---------------------------------------------------
__device__ __forceinline__ void mma16816(float c[4], const unsigned a[4],
                                         const unsigned b[2]) {
    asm volatile(
        "mma.sync.aligned.m16n8k16.row.col.f32.f16.f16.f32 "
        "{%0,%1,%2,%3}, {%4,%5,%6,%7}, {%8,%9}, {%0,%1,%2,%3};"
        : "+f"(c[0]), "+f"(c[1]), "+f"(c[2]), "+f"(c[3])
        : "r"(a[0]), "r"(a[1]), "r"(a[2]), "r"(a[3]), "r"(b[0]), "r"(b[1]));
}

__device__ __forceinline__ void ldsm_x4(unsigned r[4], unsigned addr) {
    asm volatile(
        "ldmatrix.sync.aligned.m8n8.x4.shared.b16 {%0,%1,%2,%3}, [%4];"
        : "=r"(r[0]), "=r"(r[1]), "=r"(r[2]), "=r"(r[3]) : "r"(addr));
}

__device__ __forceinline__ unsigned smem_u32(const void* p) {
    return (unsigned)__cvta_generic_to_shared(p);
}

__device__ __forceinline__ uint4 cvt8(float4 v0, float4 v1) {
    uint4 u;
    __half2 h0 = __floats2half2_rn(v0.x, v0.y);
    __half2 h1 = __floats2half2_rn(v0.z, v0.w);
    __half2 h2 = __floats2half2_rn(v1.x, v1.y);
    __half2 h3 = __floats2half2_rn(v1.z, v1.w);
    u.x = *(unsigned*)&h0; u.y = *(unsigned*)&h1;
    u.z = *(unsigned*)&h2; u.w = *(unsigned*)&h3;
    return u;
}

// ---------------------------------------------------------------------------
// GEMM1 (HMMA+LDSM, pipelined): g_t16 = half(x @ W1).
__global__ void __launch_bounds__(256) k_gemm1(const float* __restrict__ x,
                                               int n) {
    __shared__ __half As[128 * 72];
    __shared__ __half Wt[64 * WSTR];
    int tid = threadIdx.x, lane = tid & 31, wid = tid >> 5;
    int row0 = blockIdx.x * 128;
    int wr = wid & 3, wc = wid >> 2;
    int gq = lane >> 2, tq = lane & 3;
    int sub = lane >> 3, lr8 = lane & 7;

    {
        const uint4* wsrc = (const uint4*)g_W1t;
        uint4* wdst = (uint4*)Wt;
        for (int i = tid; i < 64 * WSTR / 8; i += 256) wdst[i] = wsrc[i];
    }

    unsigned a_base[2];
    {
        int arow = wr * 32 + ((sub & 1) ? 8 : 0) + lr8;
        int acol = (sub & 2) ? 8 : 0;
        a_base[0] = smem_u32(As + arow * 72 + acol);
        a_base[1] = a_base[0] + 16 * 72 * 2;
    }
    unsigned b_base[2];
    {
        int brow = wc * 32 + ((sub & 2) ? 8 : 0) + lr8;
        int bcol = (sub & 1) ? 8 : 0;
        b_base[0] = smem_u32(Wt + brow * WSTR + bcol);
        b_base[1] = b_base[0] + 16 * WSTR * 2;
    }

    float c[2][4][4];
#pragma unroll
    for (int ms = 0; ms < 2; ms++)
#pragma unroll
        for (int ns = 0; ns < 4; ns++)
#pragma unroll
            for (int q = 0; q < 4; q++) c[ms][ns][q] = 0.f;

    int lr = tid >> 1, lh = tid & 1;
    const float4* src0 =
        (const float4*)(x + (long long)(row0 + lr) * 128 + lh * 32);
    const float4* src1 = src0 + 16;
    bool ok = (row0 + lr) < n;
    uint4* dst = (uint4*)(As + lr * 72 + lh * 32);

    {
        float4 v[8];
#pragma unroll
        for (int q = 0; q < 8; q++)
            v[q] = ok ? src0[q] : make_float4(0.f, 0.f, 0.f, 0.f);
#pragma unroll
        for (int q = 0; q < 4; q++) dst[q] = cvt8(v[2 * q], v[2 * q + 1]);
    }
    float4 p[8];
#pragma unroll
    for (int q = 0; q < 8; q++)
        p[q] = ok ? src1[q] : make_float4(0.f, 0.f, 0.f, 0.f);

    __syncthreads();
#pragma unroll
    for (int ks = 0; ks < 4; ks++) {
        unsigned a[2][4], bb[2][4];
#pragma unroll
        for (int ms = 0; ms < 2; ms++) ldsm_x4(a[ms], a_base[ms] + ks * 32);
#pragma unroll
        for (int np = 0; np < 2; np++) ldsm_x4(bb[np], b_base[np] + ks * 32);
#pragma unroll
        for (int ms = 0; ms < 2; ms++)
#pragma unroll
            for (int np = 0; np < 2; np++) {
                mma16816(c[ms][np * 2],     a[ms], &bb[np][0]);
                mma16816(c[ms][np * 2 + 1], a[ms], &bb[np][2]);
            }
    }
    __syncthreads();
#pragma unroll
    for (int q = 0; q < 4; q++) dst[q] = cvt8(p[2 * q], p[2 * q + 1]);
    __syncthreads();
#pragma unroll
    for (int ks = 0; ks < 4; ks++) {
        unsigned a[2][4], bb[2][4];
#pragma unroll
        for (int ms = 0; ms < 2; ms++) ldsm_x4(a[ms], a_base[ms] + ks * 32);
#pragma unroll
        for (int np = 0; np < 2; np++)
            ldsm_x4(bb[np], b_base[np] + (64 + ks * 16) * 2);
#pragma unroll
        for (int ms = 0; ms < 2; ms++)
#pragma unroll
            for (int np = 0; np < 2; np++) {
                mma16816(c[ms][np * 2],     a[ms], &bb[np][0]);
                mma16816(c[ms][np * 2 + 1], a[ms], &bb[np][2]);
            }
    }

#pragma unroll
    for (int ms = 0; ms < 2; ms++) {
        int r = row0 + wr * 32 + ms * 16 + gq;
#pragma unroll
        for (int ns = 0; ns < 4; ns++) {
            int col = wc * 32 + ns * 8 + 2 * tq;
            if (r < n)
                *(__half2*)(g_t16 + (long long)r * 64 + col) =
                    __floats2half2_rn(c[ms][ns][0], c[ms][ns][1]);
            if (r + 8 < n)
                *(__half2*)(g_t16 + (long long)(r + 8) * 64 + col) =
                    __floats2half2_rn(c[ms][ns][2], c[ms][ns][3]);
        }
    }
}

// ---------------------------------------------------------------------------
__device__ __forceinline__ void acc8(float acc[8], uint4 v, float w) {
    const __half2* h = (const __half2*)&v;
#pragma unroll
    for (int q = 0; q < 4; q++) {
        float2 f = __half22float2(h[q]);
        acc[2 * q]     += f.x * w;
        acc[2 * q + 1] += f.y * w;
    }
}

// ---------------------------------------------------------------------------
// FUSED layer-1 agg + GEMM2: each block gathers 32 complete h rows from g_t16
// (relu(agg+b1), fp16 in smem), then does the 32x64 @ 64x64 HMMA in-block and
// writes t2 to g_t2 (SEPARATE buffer — g_t16 must stay intact while other
// blocks still gather t1 from it; in-place was the R15 race).
__global__ void __launch_bounds__(256) k_agg1g(int n, const float* __restrict__ bias) {
    __shared__ __half Hs[32 * 72];
    __shared__ __half Wt[64 * WSTR];
    int tid = threadIdx.x;
    int row0 = blockIdx.x * 32;
    int gid = row0 + (tid >> 3);
    int c = tid & 7;
    int lane = tid & 31;
    int gb = lane & 24;
    unsigned gmask = 0xFFu << gb;

    // W2t copy (overlaps with gather latency)
    {
        const uint4* wsrc = (const uint4*)g_W2t;
        uint4* wdst = (uint4*)Wt;
        for (int i = tid; i < 64 * WSTR / 8; i += 256) wdst[i] = wsrc[i];
    }

    const uint4* t4 = (const uint4*)g_t16;
    bool valid = gid < n;
    float dd = valid ? g_dinv[gid] : 0.f;
    float acc[8];
#pragma unroll
    for (int q = 0; q < 8; q++) acc[q] = 0.f;
    if (valid) acc8(acc, t4[gid * 8 + c], dd);   // self-loop

    int k = valid ? g_off[gid] : 0;
    int m = valid ? (g_deg[gid] - 1) : 0;
    for (int base = 0; base < m; base += 8) {
        int j = base + c;
        unsigned long long pc = (j < m) ? g_csr2[k + j] : 0ull;
        uint4 v[8]; float w[8];
#pragma unroll
        for (int jj = 0; jj < 8; jj++) {
            unsigned long long pj = __shfl_sync(gmask, pc, gb + jj);
            w[jj] = __uint_as_float((unsigned)(pj >> 32));
            v[jj] = t4[(int)(unsigned)pj * 8 + c];
        }
#pragma unroll
        for (int jj = 0; jj < 8; jj++) acc8(acc, v[jj], w[jj]);
    }

    // h = relu(acc*dd + b1) -> smem fp16 (zeros for invalid rows)
    {
        float4 b0 = ((const float4*)bias)[c * 2];
        float4 b1v = ((const float4*)bias)[c * 2 + 1];
        float4 o0 = make_float4(fmaxf(acc[0] * dd + b0.x, 0.f),
                                fmaxf(acc[1] * dd + b0.y, 0.f),
                                fmaxf(acc[2] * dd + b0.z, 0.f),
                                fmaxf(acc[3] * dd + b0.w, 0.f));
        float4 o1 = make_float4(fmaxf(acc[4] * dd + b1v.x, 0.f),
                                fmaxf(acc[5] * dd + b1v.y, 0.f),
                                fmaxf(acc[6] * dd + b1v.z, 0.f),
                                fmaxf(acc[7] * dd + b1v.w, 0.f));
        uint4 hv = valid ? cvt8(o0, o1) : make_uint4(0, 0, 0, 0);
        *(uint4*)(Hs + (tid >> 3) * 72 + c * 8) = hv;
    }
    __syncthreads();

    // In-block GEMM2: M=32, N=64, K=64. 8 warps = 2 row-tiles x 4 col-tiles of 16x16.
    int wid = tid >> 5;
    int wr = wid & 1, wc = wid >> 1;
    int gq = lane >> 2, tq = lane & 3;
    int sub = lane >> 3, lr8 = lane & 7;
    unsigned a_base;
    {
        int arow = wr * 16 + ((sub & 1) ? 8 : 0) + lr8;
        int acol = (sub & 2) ? 8 : 0;
        a_base = smem_u32(Hs + arow * 72 + acol);
    }
    unsigned b_base;
    {
        int brow = wc * 16 + ((sub & 2) ? 8 : 0) + lr8;
        int bcol = (sub & 1) ? 8 : 0;
        b_base = smem_u32(Wt + brow * WSTR + bcol);
    }
    float c0[4] = {0.f, 0.f, 0.f, 0.f}, c1[4] = {0.f, 0.f, 0.f, 0.f};
#pragma unroll
    for (int ks = 0; ks < 4; ks++) {
        unsigned a[4], bb[4];
        ldsm_x4(a, a_base + ks * 32);
        ldsm_x4(bb, b_base + ks * 32);
        mma16816(c0, a, &bb[0]);
        mma16816(c1, a, &bb[2]);
    }
    {
        int r = row0 + wr * 16 + gq;
        int col0 = wc * 16 + 2 * tq;
        int col1 = wc * 16 + 8 + 2 * tq;
        if (r < n) {
            *(__half2*)(g_t2 + (long long)r * 64 + col0) =
                __floats2half2_rn(c0[0], c0[1]);
            *(__half2*)(g_t2 + (long long)r * 64 + col1) =
                __floats2half2_rn(c1[0], c1[1]);
        }
        if (r + 8 < n) {
            *(__half2*)(g_t2 + (long long)(r + 8) * 64 + col0) =
                __floats2half2_rn(c0[2], c0[3]);
            *(__half2*)(g_t2 + (long long)(r + 8) * 64 + col1) =
                __floats2half2_rn(c1[2], c1[3]);
        }
    }
}

// ---------------------------------------------------------------------------
// Layer-2 aggregation: out = agg(t2) + b2 (fp32 to d_out). Reads g_t2.
__global__ void k_agg2(int n, const float* __restrict__ bias,
                       float* __restrict__ out) {
    int gid = blockIdx.x * 32 + (threadIdx.x >> 3);
    int c = threadIdx.x & 7;
    if (gid >= n) return;
    int lane = threadIdx.x & 31;
    int gb = lane & 24;
    unsigned gmask = 0xFFu << gb;

    const uint4* t4 = (const uint4*)g_t2;
    float dd = g_dinv[gid];
    float acc[8];
#pragma unroll
    for (int q = 0; q < 8; q++) acc[q] = 0.f;
    acc8(acc, t4[gid * 8 + c], dd);          // self-loop

    int k = g_off[gid];
    int m = g_deg[gid] - 1;
    for (int base = 0; base < m; base += 8) {
        int j = base + c;
        unsigned long long pc = (j < m) ? g_csr2[k + j] : 0ull;
        uint4 v[8]; float w[8];
#pragma unroll
        for (int jj = 0; jj < 8; jj++) {
            unsigned long long pj = __shfl_sync(gmask, pc, gb + jj);
            w[jj] = __uint_as_float((unsigned)(pj >> 32));
            v[jj] = t4[(int)(unsigned)pj * 8 + c];
        }
#pragma unroll
        for (int jj = 0; jj < 8; jj++) acc8(acc, v[jj], w[jj]);
    }

    float4 b0 = ((const float4*)bias)[c * 2];
    float4 b1v = ((const float4*)bias)[c * 2 + 1];
    float4 o0 = make_float4(acc[0] * dd + b0.x, acc[1] * dd + b0.y,
                            acc[2] * dd + b0.z, acc[3] * dd + b0.w);
    float4 o1 = make_float4(acc[4] * dd + b1v.x, acc[5] * dd + b1v.y,
                            acc[6] * dd + b1v.z, acc[7] * dd + b1v.w);
    float4* dst = (float4*)(out + gid * 64 + c * 8);
    dst[0] = o0; dst[1] = o1;
}

// ---------------------------------------------------------------------------
extern "C" void kernel_launch(void* const* d_in, const int* in_sizes, int n_in,
                              void* d_out, int out_size) {
    const float* x  = (const float*)d_in[0];
    const void*  ei = d_in[1];
    const float* W1 = (const float*)d_in[2];
    const float* b1 = (const float*)d_in[3];
    const float* W2 = (const float*)d_in[4];
    const float* b2 = (const float*)d_in[5];
    float* out = (float*)d_out;

    int n = in_sizes[0] / 128;
    int e = in_sizes[1] / 2;
    int nb = (n + SCAN_BLK - 1) / SCAN_BLK;
    int e4 = (e + 3) / 4;

    cudaStreamCaptureStatus cs = cudaStreamCaptureStatusNone;
    cudaStreamIsCapturing((cudaStream_t)0, &cs);
    bool fork = (cs == cudaStreamCaptureStatusActive);

    cudaStream_t s1 = 0;
    cudaEvent_t eF = 0, eJ = 0;
    if (fork) {
        cudaStreamCreateWithFlags(&s1, cudaStreamNonBlocking);
        cudaEventCreateWithFlags(&eF, cudaEventDisableTiming);
        cudaEventCreateWithFlags(&eJ, cudaEventDisableTiming);
        cudaEventRecord(eF, 0);
        cudaStreamWaitEvent(s1, eF, 0);
    }
    // Branch A (independent of edges): W transpose + GEMM1
    k_prep_w<<<48, 256, 0, s1>>>(W1, W2);
    k_gemm1<<<(n + 127) / 128, 256, 0, s1>>>(x, n);
    if (fork) cudaEventRecord(eJ, s1);

    // Branch B (edge prep)
    k_init<<<(n + 1023) / 1024, 1024>>>((const unsigned int*)ei, n);
    k_count<<<(e4 + 255) / 256, 256>>>(ei, e, n);
    k_scanlb<<<nb, SCAN_BLK>>>(n);
    k_fill<<<(e4 + 255) / 256, 256>>>(ei, e, n);

    if (fork) cudaStreamWaitEvent((cudaStream_t)0, eJ, 0);

    // Fused layer-1 agg + GEMM2 (t2 -> g_t2), then layer-2 agg (reads g_t2)
    k_agg1g<<<(n + 31) / 32, 256>>>(n, b1);
    k_agg2<<<(n + 31) / 32, 256>>>(n, b2, out);
}

// round 17
// speedup vs baseline: 1.0295x; 1.0146x over previous
#include <cuda_runtime.h>
#include <cuda_fp16.h>

#define NMAX 100000
#define EMAX 1600000
#define SCAN_BLK 256
#define MAX_BLOCKS 512   // ceil(NMAX/SCAN_BLK) = 391 <= 512
#define WSTR 136         // padded stride for W1^T (halves)
#define W2STR 72         // compact padded stride for W2^T (halves)

// Scratch (allocation-free rule: __device__ globals)
__device__ int   g_is64;
__device__ int   g_deg[NMAX];
__device__ float g_dinv[NMAX];
__device__ int   g_off[NMAX];
__device__ int   g_cur[NMAX];
__device__ unsigned long long g_part[MAX_BLOCKS];  // lookback: (flag<<32)|sum
__device__ unsigned long long g_csr2[EMAX];        // packed (src | dinv[src]<<32)
__device__ __align__(16) __half g_t16[NMAX * 64];  // t1 (layer-1 gather matrix)
__device__ __align__(16) __half g_t2[NMAX * 64];   // t2 (layer-2 gather matrix)
__device__ __align__(16) __half g_W1t[64 * WSTR];  // W1^T fp16, padded 136
__device__ __align__(16) __half g_W2t[64 * W2STR]; // W2^T fp16, padded 72

// ---------------------------------------------------------------------------
__global__ void k_init(const unsigned int* __restrict__ w, int n) {
    int i = blockIdx.x * 1024 + threadIdx.x;
    if (i < n) g_deg[i] = 1;  // self-loop
    if (i < MAX_BLOCKS) g_part[i] = 0ull;   // reset lookback state each replay
    if (blockIdx.x == 0) {
        int nz = (w[2 * threadIdx.x + 1] != 0u) ? 1 : 0;
        int tot = __syncthreads_count(nz);
        if (threadIdx.x == 0) g_is64 = (tot == 0) ? 1 : 0;
    }
}

__global__ void k_prep_w(const float* __restrict__ W1,
                         const float* __restrict__ W2) {
    int i = blockIdx.x * 256 + threadIdx.x;
    if (i < 64 * 128) {
        int nn = i >> 7, k = i & 127;
        g_W1t[nn * WSTR + k] = __float2half(W1[k * 64 + nn]);
    } else if (i < 64 * 128 + 64 * 64) {
        int j = i - 64 * 128;
        int nn = j >> 6, k = j & 63;
        g_W2t[nn * W2STR + k] = __float2half(W2[k * 64 + nn]);
    }
}

__device__ __forceinline__ int load_idx(const void* ei, long long i) {
    if (g_is64) return (int)((const long long*)ei)[i];
    return ((const int*)ei)[i];
}

__global__ void k_count(const void* __restrict__ ei, int e, int n) {
    int i4 = (blockIdx.x * blockDim.x + threadIdx.x) * 4;
    if (i4 >= e) return;
    if (!g_is64 && i4 + 4 <= e) {
        int4 d = *(const int4*)((const int*)ei + e + i4);
        if ((unsigned)d.x < (unsigned)n) atomicAdd(&g_deg[d.x], 1);
        if ((unsigned)d.y < (unsigned)n) atomicAdd(&g_deg[d.y], 1);
        if ((unsigned)d.z < (unsigned)n) atomicAdd(&g_deg[d.z], 1);
        if ((unsigned)d.w < (unsigned)n) atomicAdd(&g_deg[d.w], 1);
    } else {
        for (int i = i4; i < i4 + 4 && i < e; i++) {
            int d = load_idx(ei, (long long)e + i);
            if ((unsigned)d < (unsigned)n) atomicAdd(&g_deg[d], 1);
        }
    }
}

// --- single-pass decoupled-lookback exclusive scan of (deg-1) --------------
__global__ void k_scanlb(int n) {
    __shared__ int sh[SCAN_BLK];
    __shared__ int s_prefix;
    int t = threadIdx.x;
    int b = blockIdx.x;
    int i = b * SCAN_BLK + t;
    int d = (i < n) ? g_deg[i] : 1;
    int v = d - 1;
    sh[t] = v;
    __syncthreads();
    for (int ofs = 1; ofs < SCAN_BLK; ofs <<= 1) {
        int add = (t >= ofs) ? sh[t - ofs] : 0;
        __syncthreads();
        sh[t] += add;
        __syncthreads();
    }
    int total = sh[SCAN_BLK - 1];

    if (b == 0) {
        if (t == 0) {
            s_prefix = 0;
            atomicExch(&g_part[0], (2ull << 32) | (unsigned)total);
        }
    } else {
        if (t == 0)
            atomicExch(&g_part[b], (1ull << 32) | (unsigned)total);
        if (t < 32) {
            int prefix = 0;
            int look = b - 1;
            while (true) {
                int idx = look - t;
                unsigned long long p =
                    (idx >= 0) ? *(volatile unsigned long long*)&g_part[idx]
                               : (2ull << 32);
                unsigned flag = (unsigned)(p >> 32);
                int val = (int)(unsigned)p;
                unsigned pmask = __ballot_sync(0xFFFFFFFFu, flag == 2u);
                unsigned zmask = __ballot_sync(0xFFFFFFFFu, flag == 0u);
                if (pmask != 0) {
                    int firstP = __ffs(pmask) - 1;
                    unsigned before = (firstP == 31) ? 0x7FFFFFFFu
                                                     : ((1u << firstP) - 1u);
                    if ((zmask & before) == 0) {
                        int contrib = (t <= firstP) ? val : 0;
#pragma unroll
                        for (int o = 16; o > 0; o >>= 1)
                            contrib += __shfl_down_sync(0xFFFFFFFFu, contrib, o);
                        prefix += __shfl_sync(0xFFFFFFFFu, contrib, 0);
                        break;
                    }
                } else if (zmask == 0) {
                    int contrib = val;
#pragma unroll
                    for (int o = 16; o > 0; o >>= 1)
                        contrib += __shfl_down_sync(0xFFFFFFFFu, contrib, o);
                    prefix += __shfl_sync(0xFFFFFFFFu, contrib, 0);
                    look -= 32;
                }
            }
            if (t == 0) {
                s_prefix = prefix;
                atomicExch(&g_part[b], (2ull << 32) | (unsigned)(prefix + total));
            }
        }
    }
    __syncthreads();
    if (i < n) {
        int off = s_prefix + sh[t] - v;  // exclusive
        g_off[i] = off;
        g_cur[i] = off;
        g_dinv[i] = rsqrtf((float)d);
    }
}

__global__ void k_fill(const void* __restrict__ ei, int e, int n) {
    int i4 = (blockIdx.x * blockDim.x + threadIdx.x) * 4;
    if (i4 >= e) return;
    if (!g_is64 && i4 + 4 <= e) {
        int4 s = *(const int4*)((const int*)ei + i4);
        int4 d = *(const int4*)((const int*)ei + e + i4);
        int ss[4] = {s.x, s.y, s.z, s.w};
        int dd[4] = {d.x, d.y, d.z, d.w};
#pragma unroll
        for (int j = 0; j < 4; j++) {
            if ((unsigned)ss[j] >= (unsigned)n || (unsigned)dd[j] >= (unsigned)n)
                continue;
            int pos = atomicAdd(&g_cur[dd[j]], 1);
            if ((unsigned)pos < (unsigned)EMAX)
                g_csr2[pos] = (unsigned long long)(unsigned)ss[j] |
                              ((unsigned long long)__float_as_uint(g_dinv[ss[j]]) << 32);
        }
    } else {
        for (int i = i4; i < i4 + 4 && i < e; i++) {
            int s = load_idx(ei, i);
            int d = load_idx(ei, (long long)e + i);
            if ((unsigned)s >= (unsigned)n || (unsigned)d >= (unsigned)n) continue;
            int pos = atomicAdd(&g_cur[d], 1);
            if ((unsigned)pos < (unsigned)EMAX)
                g_csr2[pos] = (unsigned long long)(unsigned)s |
                              ((unsigned long long)__float_as_uint(g_dinv[s]) << 32);
        }
    }
}

// --- HMMA / LDSM helpers ---------------------------------------------------
__device__ __forceinline__ void mma16816(float c[4], const unsigned a[4],
                                         const unsigned b[2]) {
    asm volatile(
        "mma.sync.aligned.m16n8k16.row.col.f32.f16.f16.f32 "
        "{%0,%1,%2,%3}, {%4,%5,%6,%7}, {%8,%9}, {%0,%1,%2,%3};"
        : "+f"(c[0]), "+f"(c[1]), "+f"(c[2]), "+f"(c[3])
        : "r"(a[0]), "r"(a[1]), "r"(a[2]), "r"(a[3]), "r"(b[0]), "r"(b[1]));
}

__device__ __forceinline__ void ldsm_x4(unsigned r[4], unsigned addr) {
    asm volatile(
        "ldmatrix.sync.aligned.m8n8.x4.shared.b16 {%0,%1,%2,%3}, [%4];"
        : "=r"(r[0]), "=r"(r[1]), "=r"(r[2]), "=r"(r[3]) : "r"(addr));
}

__device__ __forceinline__ unsigned smem_u32(const void* p) {
    return (unsigned)__cvta_generic_to_shared(p);
}

__device__ __forceinline__ uint4 cvt8(float4 v0, float4 v1) {
    uint4 u;
    __half2 h0 = __floats2half2_rn(v0.x, v0.y);
    __half2 h1 = __floats2half2_rn(v0.z, v0.w);
    __half2 h2 = __floats2half2_rn(v1.x, v1.y);
    __half2 h3 = __floats2half2_rn(v1.z, v1.w);
    u.x = *(unsigned*)&h0; u.y = *(unsigned*)&h1;
    u.z = *(unsigned*)&h2; u.w = *(unsigned*)&h3;
    return u;
}

// ---------------------------------------------------------------------------
// GEMM1 (HMMA+LDSM, pipelined): g_t16 = half(x @ W1).
__global__ void __launch_bounds__(256) k_gemm1(const float* __restrict__ x,
                                               int n) {
    __shared__ __half As[128 * 72];
    __shared__ __half Wt[64 * WSTR];
    int tid = threadIdx.x, lane = tid & 31, wid = tid >> 5;
    int row0 = blockIdx.x * 128;
    int wr = wid & 3, wc = wid >> 2;
    int gq = lane >> 2, tq = lane & 3;
    int sub = lane >> 3, lr8 = lane & 7;

    {
        const uint4* wsrc = (const uint4*)g_W1t;
        uint4* wdst = (uint4*)Wt;
        for (int i = tid; i < 64 * WSTR / 8; i += 256) wdst[i] = wsrc[i];
    }

    unsigned a_base[2];
    {
        int arow = wr * 32 + ((sub & 1) ? 8 : 0) + lr8;
        int acol = (sub & 2) ? 8 : 0;
        a_base[0] = smem_u32(As + arow * 72 + acol);
        a_base[1] = a_base[0] + 16 * 72 * 2;
    }
    unsigned b_base[2];
    {
        int brow = wc * 32 + ((sub & 2) ? 8 : 0) + lr8;
        int bcol = (sub & 1) ? 8 : 0;
        b_base[0] = smem_u32(Wt + brow * WSTR + bcol);
        b_base[1] = b_base[0] + 16 * WSTR * 2;
    }

    float c[2][4][4];
#pragma unroll
    for (int ms = 0; ms < 2; ms++)
#pragma unroll
        for (int ns = 0; ns < 4; ns++)
#pragma unroll
            for (int q = 0; q < 4; q++) c[ms][ns][q] = 0.f;

    int lr = tid >> 1, lh = tid & 1;
    const float4* src0 =
        (const float4*)(x + (long long)(row0 + lr) * 128 + lh * 32);
    const float4* src1 = src0 + 16;
    bool ok = (row0 + lr) < n;
    uint4* dst = (uint4*)(As + lr * 72 + lh * 32);

    {
        float4 v[8];
#pragma unroll
        for (int q = 0; q < 8; q++)
            v[q] = ok ? src0[q] : make_float4(0.f, 0.f, 0.f, 0.f);
#pragma unroll
        for (int q = 0; q < 4; q++) dst[q] = cvt8(v[2 * q], v[2 * q + 1]);
    }
    float4 p[8];
#pragma unroll
    for (int q = 0; q < 8; q++)
        p[q] = ok ? src1[q] : make_float4(0.f, 0.f, 0.f, 0.f);

    __syncthreads();
#pragma unroll
    for (int ks = 0; ks < 4; ks++) {
        unsigned a[2][4], bb[2][4];
#pragma unroll
        for (int ms = 0; ms < 2; ms++) ldsm_x4(a[ms], a_base[ms] + ks * 32);
#pragma unroll
        for (int np = 0; np < 2; np++) ldsm_x4(bb[np], b_base[np] + ks * 32);
#pragma unroll
        for (int ms = 0; ms < 2; ms++)
#pragma unroll
            for (int np = 0; np < 2; np++) {
                mma16816(c[ms][np * 2],     a[ms], &bb[np][0]);
                mma16816(c[ms][np * 2 + 1], a[ms], &bb[np][2]);
            }
    }
    __syncthreads();
#pragma unroll
    for (int q = 0; q < 4; q++) dst[q] = cvt8(p[2 * q], p[2 * q + 1]);
    __syncthreads();
#pragma unroll
    for (int ks = 0; ks < 4; ks++) {
        unsigned a[2][4], bb[2][4];
#pragma unroll
        for (int ms = 0; ms < 2; ms++) ldsm_x4(a[ms], a_base[ms] + ks * 32);
#pragma unroll
        for (int np = 0; np < 2; np++)
            ldsm_x4(bb[np], b_base[np] + (64 + ks * 16) * 2);
#pragma unroll
        for (int ms = 0; ms < 2; ms++)
#pragma unroll
            for (int np = 0; np < 2; np++) {
                mma16816(c[ms][np * 2],     a[ms], &bb[np][0]);
                mma16816(c[ms][np * 2 + 1], a[ms], &bb[np][2]);
            }
    }

#pragma unroll
    for (int ms = 0; ms < 2; ms++) {
        int r = row0 + wr * 32 + ms * 16 + gq;
#pragma unroll
        for (int ns = 0; ns < 4; ns++) {
            int col = wc * 32 + ns * 8 + 2 * tq;
            if (r < n)
                *(__half2*)(g_t16 + (long long)r * 64 + col) =
                    __floats2half2_rn(c[ms][ns][0], c[ms][ns][1]);
            if (r + 8 < n)
                *(__half2*)(g_t16 + (long long)(r + 8) * 64 + col) =
                    __floats2half2_rn(c[ms][ns][2], c[ms][ns][3]);
        }
    }
}

// ---------------------------------------------------------------------------
__device__ __forceinline__ void acc8(float acc[8], uint4 v, float w) {
    const __half2* h = (const __half2*)&v;
#pragma unroll
    for (int q = 0; q < 4; q++) {
        float2 f = __half22float2(h[q]);
        acc[2 * q]     += f.x * w;
        acc[2 * q + 1] += f.y * w;
    }
}

// ---------------------------------------------------------------------------
// FUSED layer-1 agg + GEMM2, 64 nodes per block (512 threads):
// gather h rows -> smem fp16, in-block 64x64 @ 64x64 HMMA (16 warps, one
// 16x16 tile each), t2 -> g_t2. Compact W2 (stride 72) halves the per-block
// weight copy; 64 rows/block halves the number of copies.
__global__ void __launch_bounds__(512) k_agg1g(int n, const float* __restrict__ bias) {
    __shared__ __half Hs[64 * 72];
    __shared__ __half Wt[64 * W2STR];
    int tid = threadIdx.x;
    int row0 = blockIdx.x * 64;
    int gid = row0 + (tid >> 3);
    int c = tid & 7;
    int lane = tid & 31;
    int gb = lane & 24;
    unsigned gmask = 0xFFu << gb;

    // W2t copy (compact, overlaps with gather latency)
    {
        const uint4* wsrc = (const uint4*)g_W2t;
        uint4* wdst = (uint4*)Wt;
        for (int i = tid; i < 64 * W2STR / 8; i += 512) wdst[i] = wsrc[i];
    }

    const uint4* t4 = (const uint4*)g_t16;
    bool valid = gid < n;
    float dd = valid ? g_dinv[gid] : 0.f;
    float acc[8];
#pragma unroll
    for (int q = 0; q < 8; q++) acc[q] = 0.f;
    if (valid) acc8(acc, t4[gid * 8 + c], dd);   // self-loop

    int k = valid ? g_off[gid] : 0;
    int m = valid ? (g_deg[gid] - 1) : 0;
    for (int base = 0; base < m; base += 8) {
        int j = base + c;
        unsigned long long pc = (j < m) ? g_csr2[k + j] : 0ull;
        uint4 v[8]; float w[8];
#pragma unroll
        for (int jj = 0; jj < 8; jj++) {
            unsigned long long pj = __shfl_sync(gmask, pc, gb + jj);
            w[jj] = __uint_as_float((unsigned)(pj >> 32));
            v[jj] = t4[(int)(unsigned)pj * 8 + c];
        }
#pragma unroll
        for (int jj = 0; jj < 8; jj++) acc8(acc, v[jj], w[jj]);
    }

    // h = relu(acc*dd + b1) -> smem fp16 (zeros for invalid rows)
    {
        float4 b0 = ((const float4*)bias)[c * 2];
        float4 b1v = ((const float4*)bias)[c * 2 + 1];
        float4 o0 = make_float4(fmaxf(acc[0] * dd + b0.x, 0.f),
                                fmaxf(acc[1] * dd + b0.y, 0.f),
                                fmaxf(acc[2] * dd + b0.z, 0.f),
                                fmaxf(acc[3] * dd + b0.w, 0.f));
        float4 o1 = make_float4(fmaxf(acc[4] * dd + b1v.x, 0.f),
                                fmaxf(acc[5] * dd + b1v.y, 0.f),
                                fmaxf(acc[6] * dd + b1v.z, 0.f),
                                fmaxf(acc[7] * dd + b1v.w, 0.f));
        uint4 hv = valid ? cvt8(o0, o1) : make_uint4(0, 0, 0, 0);
        *(uint4*)(Hs + (tid >> 3) * 72 + c * 8) = hv;
    }
    __syncthreads();

    // In-block GEMM2: M=64, N=64, K=64. 16 warps = 4 row x 4 col tiles of 16x16.
    int wid = tid >> 5;
    int wr = wid & 3, wc = wid >> 2;
    int gq = lane >> 2, tq = lane & 3;
    int sub = lane >> 3, lr8 = lane & 7;
    unsigned a_base;
    {
        int arow = wr * 16 + ((sub & 1) ? 8 : 0) + lr8;
        int acol = (sub & 2) ? 8 : 0;
        a_base = smem_u32(Hs + arow * 72 + acol);
    }
    unsigned b_base;
    {
        int brow = wc * 16 + ((sub & 2) ? 8 : 0) + lr8;
        int bcol = (sub & 1) ? 8 : 0;
        b_base = smem_u32(Wt + brow * W2STR + bcol);
    }
    float c0[4] = {0.f, 0.f, 0.f, 0.f}, c1[4] = {0.f, 0.f, 0.f, 0.f};
#pragma unroll
    for (int ks = 0; ks < 4; ks++) {
        unsigned a[4], bb[4];
        ldsm_x4(a, a_base + ks * 32);
        ldsm_x4(bb, b_base + ks * 32);
        mma16816(c0, a, &bb[0]);
        mma16816(c1, a, &bb[2]);
    }
    {
        int r = row0 + wr * 16 + gq;
        int col0 = wc * 16 + 2 * tq;
        int col1 = wc * 16 + 8 + 2 * tq;
        if (r < n) {
            *(__half2*)(g_t2 + (long long)r * 64 + col0) =
                __floats2half2_rn(c0[0], c0[1]);
            *(__half2*)(g_t2 + (long long)r * 64 + col1) =
                __floats2half2_rn(c1[0], c1[1]);
        }
        if (r + 8 < n) {
            *(__half2*)(g_t2 + (long long)(r + 8) * 64 + col0) =
                __floats2half2_rn(c0[2], c0[3]);
            *(__half2*)(g_t2 + (long long)(r + 8) * 64 + col1) =
                __floats2half2_rn(c1[2], c1[3]);
        }
    }
}

// ---------------------------------------------------------------------------
// Layer-2 aggregation: out = agg(t2) + b2 (fp32 to d_out). Reads g_t2.
__global__ void k_agg2(int n, const float* __restrict__ bias,
                       float* __restrict__ out) {
    int gid = blockIdx.x * 32 + (threadIdx.x >> 3);
    int c = threadIdx.x & 7;
    if (gid >= n) return;
    int lane = threadIdx.x & 31;
    int gb = lane & 24;
    unsigned gmask = 0xFFu << gb;

    const uint4* t4 = (const uint4*)g_t2;
    float dd = g_dinv[gid];
    float acc[8];
#pragma unroll
    for (int q = 0; q < 8; q++) acc[q] = 0.f;
    acc8(acc, t4[gid * 8 + c], dd);          // self-loop

    int k = g_off[gid];
    int m = g_deg[gid] - 1;
    for (int base = 0; base < m; base += 8) {
        int j = base + c;
        unsigned long long pc = (j < m) ? g_csr2[k + j] : 0ull;
        uint4 v[8]; float w[8];
#pragma unroll
        for (int jj = 0; jj < 8; jj++) {
            unsigned long long pj = __shfl_sync(gmask, pc, gb + jj);
            w[jj] = __uint_as_float((unsigned)(pj >> 32));
            v[jj] = t4[(int)(unsigned)pj * 8 + c];
        }
#pragma unroll
        for (int jj = 0; jj < 8; jj++) acc8(acc, v[jj], w[jj]);
    }

    float4 b0 = ((const float4*)bias)[c * 2];
    float4 b1v = ((const float4*)bias)[c * 2 + 1];
    float4 o0 = make_float4(acc[0] * dd + b0.x, acc[1] * dd + b0.y,
                            acc[2] * dd + b0.z, acc[3] * dd + b0.w);
    float4 o1 = make_float4(acc[4] * dd + b1v.x, acc[5] * dd + b1v.y,
                            acc[6] * dd + b1v.z, acc[7] * dd + b1v.w);
    float4* dst = (float4*)(out + gid * 64 + c * 8);
    dst[0] = o0; dst[1] = o1;
}

// ---------------------------------------------------------------------------
extern "C" void kernel_launch(void* const* d_in, const int* in_sizes, int n_in,
                              void* d_out, int out_size) {
    const float* x  = (const float*)d_in[0];
    const void*  ei = d_in[1];
    const float* W1 = (const float*)d_in[2];
    const float* b1 = (const float*)d_in[3];
    const float* W2 = (const float*)d_in[4];
    const float* b2 = (const float*)d_in[5];
    float* out = (float*)d_out;

    int n = in_sizes[0] / 128;
    int e = in_sizes[1] / 2;
    int nb = (n + SCAN_BLK - 1) / SCAN_BLK;
    int e4 = (e + 3) / 4;

    cudaStreamCaptureStatus cs = cudaStreamCaptureStatusNone;
    cudaStreamIsCapturing((cudaStream_t)0, &cs);
    bool fork = (cs == cudaStreamCaptureStatusActive);

    cudaStream_t s1 = 0;
    cudaEvent_t eF = 0, eJ = 0;
    if (fork) {
        cudaStreamCreateWithFlags(&s1, cudaStreamNonBlocking);
        cudaEventCreateWithFlags(&eF, cudaEventDisableTiming);
        cudaEventCreateWithFlags(&eJ, cudaEventDisableTiming);
        cudaEventRecord(eF, 0);
        cudaStreamWaitEvent(s1, eF, 0);
    }
    // Branch A (independent of edges): W transpose + GEMM1
    k_prep_w<<<48, 256, 0, s1>>>(W1, W2);
    k_gemm1<<<(n + 127) / 128, 256, 0, s1>>>(x, n);
    if (fork) cudaEventRecord(eJ, s1);

    // Branch B (edge prep)
    k_init<<<(n + 1023) / 1024, 1024>>>((const unsigned int*)ei, n);
    k_count<<<(e4 + 255) / 256, 256>>>(ei, e, n);
    k_scanlb<<<nb, SCAN_BLK>>>(n);
    k_fill<<<(e4 + 255) / 256, 256>>>(ei, e, n);

    if (fork) cudaStreamWaitEvent((cudaStream_t)0, eJ, 0);

    // Fused layer-1 agg + GEMM2 (t2 -> g_t2), then layer-2 agg (reads g_t2)
    k_agg1g<<<(n + 63) / 64, 512>>>(n, b1);
    k_agg2<<<(n + 31) / 32, 256>>>(n, b2, out);
}